// round 1
// baseline (speedup 1.0000x reference)
#include <cuda_runtime.h>
#include <cstdint>

#define C   128
#define NN  50000
#define NE  600000

// ---------------- device scratch (no allocations allowed) ----------------
__device__ __align__(16) float g_agg[3 * NN * C];   // 0: ui(dst=item) 1: iu(dst=user) 2: uu(dst=user)
__device__ __align__(16) float g_x[2 * NN * C];     // layer outputs: [0]=user [1]=item
__device__ __align__(16) float g_W[C * 384 + C * 256];
__device__ float g_b[2 * C];
__device__ int   g_deg[3 * NN];
__device__ int   g_rowptr[3 * (NN + 1)];
__device__ int   g_cursor[3 * NN];
__device__ int   g_srcs[3 * NE];

// ---------------- CSR build ----------------
__global__ void zero_int(int* p, int n) {
    for (int i = blockIdx.x * blockDim.x + threadIdx.x; i < n; i += gridDim.x * blockDim.x) p[i] = 0;
}

__global__ void histo(const int* __restrict__ dst, int* __restrict__ deg, int n) {
    for (int i = blockIdx.x * blockDim.x + threadIdx.x; i < n; i += gridDim.x * blockDim.x)
        atomicAdd(&deg[dst[i]], 1);
}

// single-block chunked Hillis-Steele exclusive scan
__global__ void scan1(const int* __restrict__ deg, int* __restrict__ rowptr, int* __restrict__ cursor, int n) {
    __shared__ int sh[1024];
    int t = threadIdx.x;
    int running = 0;
    for (int base = 0; base < n; base += 1024) {
        int v = (base + t < n) ? deg[base + t] : 0;
        sh[t] = v;
        __syncthreads();
        for (int off = 1; off < 1024; off <<= 1) {
            int x = (t >= off) ? sh[t - off] : 0;
            __syncthreads();
            sh[t] += x;
            __syncthreads();
        }
        if (base + t < n) {
            int r = running + sh[t] - v;
            rowptr[base + t] = r;
            cursor[base + t] = r;
        }
        running += sh[1023];
        __syncthreads();
    }
    if (t == 0) rowptr[n] = running;
}

__global__ void fillcsr(const int* __restrict__ src, const int* __restrict__ dst,
                        int* __restrict__ cursor, int* __restrict__ srcs, int n) {
    for (int i = blockIdx.x * blockDim.x + threadIdx.x; i < n; i += gridDim.x * blockDim.x) {
        int p = atomicAdd(&cursor[dst[i]], 1);
        srcs[p] = src[i];
    }
}

// ---------------- mean aggregation: one warp per dst node ----------------
__device__ __forceinline__ void f4add(float4& a, const float4 b) {
    a.x += b.x; a.y += b.y; a.z += b.z; a.w += b.w;
}

__global__ void aggregate(const float* __restrict__ xsrc, const int* __restrict__ rowptr,
                          const int* __restrict__ srcs, float* __restrict__ meanout, int n) {
    int w = (blockIdx.x * blockDim.x + threadIdx.x) >> 5;
    int lane = threadIdx.x & 31;
    if (w >= n) return;
    int beg = rowptr[w], end = rowptr[w + 1];
    float4 a0 = {0.f, 0.f, 0.f, 0.f}, a1 = a0, a2 = a0, a3 = a0;
    int e = beg;
    for (; e + 4 <= end; e += 4) {
        int s0 = srcs[e], s1 = srcs[e + 1], s2 = srcs[e + 2], s3 = srcs[e + 3];
        float4 v0 = ((const float4*)(xsrc + (size_t)s0 * C))[lane];
        float4 v1 = ((const float4*)(xsrc + (size_t)s1 * C))[lane];
        float4 v2 = ((const float4*)(xsrc + (size_t)s2 * C))[lane];
        float4 v3 = ((const float4*)(xsrc + (size_t)s3 * C))[lane];
        f4add(a0, v0); f4add(a1, v1); f4add(a2, v2); f4add(a3, v3);
    }
    for (; e < end; ++e) {
        int s = srcs[e];
        f4add(a0, ((const float4*)(xsrc + (size_t)s * C))[lane]);
    }
    f4add(a0, a1); f4add(a2, a3); f4add(a0, a2);
    int d = end - beg;
    float inv = 1.0f / (float)(d > 1 ? d : 1);
    float4 r = {a0.x * inv, a0.y * inv, a0.z * inv, a0.w * inv};
    ((float4*)(meanout + (size_t)w * C))[lane] = r;
}

// ---------------- weight pre-concat ----------------
__global__ void prep_user(const float* __restrict__ Wl_iu, const float* __restrict__ b_iu, const float* __restrict__ Wr_iu,
                          const float* __restrict__ Wl_uu, const float* __restrict__ b_uu, const float* __restrict__ Wr_uu) {
    int i = blockIdx.x * blockDim.x + threadIdx.x;
    if (i < C * 384) {
        int c = i / 384, k = i - c * 384;
        float v;
        if (k < 128)      v = Wl_iu[c * 128 + k];
        else if (k < 256) v = Wl_uu[c * 128 + k - 128];
        else              v = Wr_iu[c * 128 + k - 256] + Wr_uu[c * 128 + k - 256];
        g_W[i] = v;
        if (i < C) g_b[i] = b_iu[i] + b_uu[i];
    }
}

__global__ void prep_item(const float* __restrict__ Wl_ui, const float* __restrict__ b_ui, const float* __restrict__ Wr_ui) {
    int i = blockIdx.x * blockDim.x + threadIdx.x;
    if (i < C * 256) {
        int c = i / 256, k = i - c * 256;
        g_W[C * 384 + i] = (k < 128) ? Wl_ui[c * 128 + k] : Wr_ui[c * 128 + k - 128];
        if (i < C) g_b[C + i] = b_ui[i];
    }
}

// ---------------- packed fp32x2 helpers ----------------
__device__ __forceinline__ unsigned long long dup2(float w) {
    unsigned long long r;
    asm("mov.b64 %0, {%1, %1};" : "=l"(r) : "f"(w));
    return r;
}
__device__ __forceinline__ unsigned long long pk2(float a, float b) {
    unsigned long long r;
    asm("mov.b64 %0, {%1, %2};" : "=l"(r) : "f"(a), "f"(b));
    return r;
}
__device__ __forceinline__ void fma2(unsigned long long& acc, unsigned long long w, unsigned long long x) {
    asm("fma.rn.f32x2 %0, %1, %2, %0;" : "+l"(acc) : "l"(w), "l"(x));
}
__device__ __forceinline__ void unpk2(unsigned long long v, float& a, float& b) {
    asm("mov.b64 {%0, %1}, %2;" : "=f"(a), "=f"(b) : "l"(v));
}

// ---------------- fused GEMM + bias + LayerNorm + ReLU ----------------
// out[n][c] = relu(LN_c( sum_k cat(A0,A1,A2)[n][k] * W[c][k] + bias[c] ))
// block: 128 threads, 32 nodes. thread (cg,ng): channels cg*4..+3, node-pairs ng*4..+3.
// K streamed in 64-wide chunks: sWt 32KB + sXq 8KB (static smem, no attr needed).
template <int NCHUNK>
__global__ void __launch_bounds__(128)
gemm_ln_relu(const float* __restrict__ A0, const float* __restrict__ A1, const float* __restrict__ A2,
             const float* __restrict__ lnw, const float* __restrict__ lnb,
             float* __restrict__ out, int n) {
    __shared__ float sWt[16 * 512];   // 8192 floats: [k4][c][kk] float4-blocked
    __shared__ float sXq[2048];       // [k4][pair][kk] float2 node pairs
    __shared__ float smu[32], srs[32];

    const float* W    = (NCHUNK == 3) ? g_W : (g_W + C * 384);
    const float* bias = (NCHUNK == 3) ? g_b : (g_b + C);
    const int KTOT = NCHUNK * 128;

    int tid = threadIdx.x;
    int cg = tid & 31, ng = tid >> 5;
    int node_base = blockIdx.x * 32;

    unsigned long long acc[4][4];
#pragma unroll
    for (int i = 0; i < 4; i++)
#pragma unroll
        for (int j = 0; j < 4; j++) acc[i][j] = 0ULL;

    const float* As[3] = {A0, A1, A2};

#pragma unroll
    for (int ch = 0; ch < 2 * NCHUNK; ch++) {
        const float* A = As[ch >> 1];
        int koff = (ch & 1) * 64;

        // load W chunk transposed/blocked: sWt[(k>>2)*512 + c*4 + (k&3)]
#pragma unroll 8
        for (int i = 0; i < 64; i++) {
            int idx = i * 128 + tid;
            int c = idx >> 6, k = idx & 63;
            sWt[(k >> 2) * 512 + c * 4 + (k & 3)] = W[c * KTOT + ch * 64 + k];
        }
        // load X chunk as node-pair float2s: sXq[(k>>2)*128 + pair*8 + (k&3)*2 + sub]
#pragma unroll 8
        for (int i = 0; i < 16; i++) {
            int idx = i * 128 + tid;
            int nl = idx >> 6, k = idx & 63;
            int nidx = node_base + nl;
            float v = (nidx < n) ? A[(size_t)nidx * C + koff + k] : 0.f;
            sXq[(k >> 2) * 128 + (nl >> 1) * 8 + (k & 3) * 2 + (nl & 1)] = v;
        }
        __syncthreads();

        const float4* Wt4 = (const float4*)sWt;
        const float4* Xq4 = (const float4*)sXq;
#pragma unroll 4
        for (int k4 = 0; k4 < 16; k4++) {
            unsigned long long wd[4][4];
#pragma unroll
            for (int ci = 0; ci < 4; ci++) {
                float4 w = Wt4[k4 * 128 + cg * 4 + ci];
                wd[ci][0] = dup2(w.x); wd[ci][1] = dup2(w.y);
                wd[ci][2] = dup2(w.z); wd[ci][3] = dup2(w.w);
            }
#pragma unroll
            for (int pi = 0; pi < 4; pi++) {
                int pair = ng * 4 + pi;
                float4 xA = Xq4[k4 * 32 + pair * 2];
                float4 xB = Xq4[k4 * 32 + pair * 2 + 1];
                unsigned long long x0 = pk2(xA.x, xA.y), x1 = pk2(xA.z, xA.w);
                unsigned long long x2 = pk2(xB.x, xB.y), x3 = pk2(xB.z, xB.w);
#pragma unroll
                for (int ci = 0; ci < 4; ci++) {
                    fma2(acc[ci][pi], wd[ci][0], x0);
                    fma2(acc[ci][pi], wd[ci][1], x1);
                    fma2(acc[ci][pi], wd[ci][2], x2);
                    fma2(acc[ci][pi], wd[ci][3], x3);
                }
            }
        }
        __syncthreads();
    }

    // epilogue: stage y (+bias) into smem (reuse sWt), LN per node, ReLU, store
    float* ys = sWt;
    float bsv[4];
#pragma unroll
    for (int ci = 0; ci < 4; ci++) bsv[ci] = bias[cg * 4 + ci];
#pragma unroll
    for (int ci = 0; ci < 4; ci++) {
        int c = cg * 4 + ci;
#pragma unroll
        for (int pi = 0; pi < 4; pi++) {
            int pair = ng * 4 + pi;
            float lo, hi;
            unpk2(acc[ci][pi], lo, hi);
            ys[(pair * 2 + 0) * 128 + c] = lo + bsv[ci];
            ys[(pair * 2 + 1) * 128 + c] = hi + bsv[ci];
        }
    }
    __syncthreads();

    {   // 4 lanes per node reduce mean/var
        int nd = tid >> 2, q = tid & 3;
        float s = 0.f, s2 = 0.f;
#pragma unroll
        for (int i = 0; i < 32; i++) {
            int j = (i + tid) & 31;  // bank-rotation
            float v = ys[nd * 128 + q * 32 + j];
            s += v; s2 += v * v;
        }
        s  += __shfl_xor_sync(0xffffffffu, s, 1);
        s  += __shfl_xor_sync(0xffffffffu, s, 2);
        s2 += __shfl_xor_sync(0xffffffffu, s2, 1);
        s2 += __shfl_xor_sync(0xffffffffu, s2, 2);
        if (q == 0) {
            float mu = s * (1.f / 128.f);
            float var = s2 * (1.f / 128.f) - mu * mu;
            smu[nd] = mu;
            srs[nd] = rsqrtf(var + 1e-5f);
        }
    }
    __syncthreads();

    float lw = lnw[tid], lb = lnb[tid];
#pragma unroll 4
    for (int nd = 0; nd < 32; nd++) {
        int nidx = node_base + nd;
        if (nidx < n) {
            float v = (ys[nd * 128 + tid] - smu[nd]) * srs[nd] * lw + lb;
            out[(size_t)nidx * C + tid] = fmaxf(v, 0.f);
        }
    }
}

// ---------------- host launch ----------------
extern "C" void kernel_launch(void* const* d_in, const int* in_sizes, int n_in,
                              void* d_out, int out_size) {
    const float* x_user = (const float*)d_in[0];
    const float* x_item = (const float*)d_in[1];
    const int* EI[3] = {(const int*)d_in[2], (const int*)d_in[3], (const int*)d_in[4]};

    int *deg, *rowptr, *cursor, *srcs;
    float *agg, *xbuf;
    cudaGetSymbolAddress((void**)&deg, g_deg);
    cudaGetSymbolAddress((void**)&rowptr, g_rowptr);
    cudaGetSymbolAddress((void**)&cursor, g_cursor);
    cudaGetSymbolAddress((void**)&srcs, g_srcs);
    cudaGetSymbolAddress((void**)&agg, g_agg);
    cudaGetSymbolAddress((void**)&xbuf, g_x);

    float* agg_ui = agg;
    float* agg_iu = agg + (size_t)NN * C;
    float* agg_uu = agg + (size_t)2 * NN * C;
    float* xu = xbuf;
    float* xi = xbuf + (size_t)NN * C;

    // ---- CSR build (edge structure shared by both layers) ----
    zero_int<<<256, 256>>>(deg, 3 * NN);
    for (int t = 0; t < 3; t++)
        histo<<<512, 256>>>(EI[t] + NE, deg + t * NN, NE);
    for (int t = 0; t < 3; t++)
        scan1<<<1, 1024>>>(deg + t * NN, rowptr + t * (NN + 1), cursor + t * NN, NN);
    for (int t = 0; t < 3; t++)
        fillcsr<<<512, 256>>>(EI[t], EI[t] + NE, cursor + t * NN, srcs + t * NE, NE);

    const int AGG_GRID = (NN + 7) / 8;     // warp per node, 8 warps/block
    const int GEMM_GRID = (NN + 31) / 32;

    for (int layer = 0; layer < 2; layer++) {
        const float* xu_in = (layer == 0) ? x_user : xu;
        const float* xi_in = (layer == 0) ? x_item : xi;
        int base = 5 + layer * 13;
        const float* Wl_ui = (const float*)d_in[base + 0];
        const float* b_ui  = (const float*)d_in[base + 1];
        const float* Wr_ui = (const float*)d_in[base + 2];
        const float* Wl_iu = (const float*)d_in[base + 3];
        const float* b_iu  = (const float*)d_in[base + 4];
        const float* Wr_iu = (const float*)d_in[base + 5];
        const float* Wl_uu = (const float*)d_in[base + 6];
        const float* b_uu  = (const float*)d_in[base + 7];
        const float* Wr_uu = (const float*)d_in[base + 8];
        const float* lnw_u = (const float*)d_in[base + 9];
        const float* lnb_u = (const float*)d_in[base + 10];
        const float* lnw_i = (const float*)d_in[base + 11];
        const float* lnb_i = (const float*)d_in[base + 12];

        prep_user<<<(C * 384 + 255) / 256, 256>>>(Wl_iu, b_iu, Wr_iu, Wl_uu, b_uu, Wr_uu);
        prep_item<<<(C * 256 + 255) / 256, 256>>>(Wl_ui, b_ui, Wr_ui);

        aggregate<<<AGG_GRID, 256>>>(xu_in, rowptr + 0 * (NN + 1), srcs + 0 * NE, agg_ui, NN); // u->i
        aggregate<<<AGG_GRID, 256>>>(xi_in, rowptr + 1 * (NN + 1), srcs + 1 * NE, agg_iu, NN); // i->u
        aggregate<<<AGG_GRID, 256>>>(xu_in, rowptr + 2 * (NN + 1), srcs + 2 * NE, agg_uu, NN); // u->u

        float* out_u = (layer == 0) ? xu : ((float*)d_out);
        float* out_i = (layer == 0) ? xi : ((float*)d_out + (size_t)NN * C);
        gemm_ln_relu<3><<<GEMM_GRID, 128>>>(agg_iu, agg_uu, xu_in, lnw_u, lnb_u, out_u, NN);
        gemm_ln_relu<2><<<GEMM_GRID, 128>>>(agg_ui, xi_in, nullptr, lnw_i, lnb_i, out_i, NN);
    }
}

// round 3
// speedup vs baseline: 3.0002x; 3.0002x over previous
#include <cuda_runtime.h>
#include <cuda_bf16.h>
#include <cstdint>

#define C   128
#define NN  50000
#define NE  600000
#define NB  49          // ceil(NN/1024)

// ---------------- device scratch (no allocations allowed) ----------------
__device__ __align__(16) float g_agg[3 * NN * C];   // 0: ui(dst=item) 1: iu(dst=user) 2: uu(dst=user)
__device__ __align__(16) float g_x[2 * NN * C];     // layer outputs: [0]=user [1]=item
__device__ __align__(16) __nv_bfloat16 g_Wu_hi[C * 384];
__device__ __align__(16) __nv_bfloat16 g_Wu_lo[C * 384];
__device__ __align__(16) __nv_bfloat16 g_Wi_hi[C * 256];
__device__ __align__(16) __nv_bfloat16 g_Wi_lo[C * 256];
__device__ float g_b[2 * C];
__device__ int   g_deg[3 * NN];
__device__ int   g_rowptr[3 * (NN + 1)];
__device__ int   g_cursor[3 * NN];
__device__ int   g_srcs[3 * NE];
__device__ int   g_bsum[3 * 64];
__device__ int   g_bofs[3 * 64];

// ---------------- CSR build ----------------
__global__ void zero_int(int* p, int n) {
    for (int i = blockIdx.x * blockDim.x + threadIdx.x; i < n; i += gridDim.x * blockDim.x) p[i] = 0;
}

__global__ void histo(const int* __restrict__ dst, int* __restrict__ deg, int n) {
    for (int i = blockIdx.x * blockDim.x + threadIdx.x; i < n; i += gridDim.x * blockDim.x)
        atomicAdd(&deg[dst[i]], 1);
}

// phase 1: per-1024-block sums, all 3 edge types at once
__global__ void scan_partial(const int* __restrict__ deg, int* __restrict__ bsum) {
    int z = blockIdx.y, b = blockIdx.x, t = threadIdx.x;
    int lane = t & 31, wid = t >> 5;
    int s = 0;
#pragma unroll
    for (int q = 0; q < 4; q++) {
        int i = b * 1024 + q * 256 + t;
        if (i < NN) s += deg[z * NN + i];
    }
    for (int o = 16; o; o >>= 1) s += __shfl_down_sync(0xffffffffu, s, o);
    __shared__ int ws[8];
    if (lane == 0) ws[wid] = s;
    __syncthreads();
    if (t == 0) {
        int tot = 0;
#pragma unroll
        for (int w = 0; w < 8; w++) tot += ws[w];
        bsum[z * 64 + b] = tot;
    }
}

// phase 2: exclusive scan of the 49 block sums per type (1 warp per type)
__global__ void scan_bsum(const int* __restrict__ bsum, int* __restrict__ bofs) {
    int t = threadIdx.x;
    int z = t >> 5, lane = t & 31;
    if (z < 3) {
        int carry = 0;
        for (int bb = 0; bb < 64; bb += 32) {
            int idx = bb + lane;
            int v = (idx < NB) ? bsum[z * 64 + idx] : 0;
            int incl = v;
            for (int o = 1; o < 32; o <<= 1) {
                int x = __shfl_up_sync(0xffffffffu, incl, o);
                if (lane >= o) incl += x;
            }
            if (idx < 64) bofs[z * 64 + idx] = carry + incl - v;
            carry += __shfl_sync(0xffffffffu, incl, 31);
        }
    }
}

// phase 3: block-local exclusive scan + offset -> rowptr/cursor
__global__ void scan_final(const int* __restrict__ deg, const int* __restrict__ bofs,
                           int* __restrict__ rowptr, int* __restrict__ cursor) {
    int z = blockIdx.y, b = blockIdx.x, t = threadIdx.x;
    int lane = t & 31, wid = t >> 5;
    int base = b * 1024 + t * 4;
    int v[4]; int tsum = 0;
#pragma unroll
    for (int q = 0; q < 4; q++) {
        int i = base + q;
        v[q] = (i < NN) ? deg[z * NN + i] : 0;
        tsum += v[q];
    }
    int incl = tsum;
    for (int o = 1; o < 32; o <<= 1) {
        int x = __shfl_up_sync(0xffffffffu, incl, o);
        if (lane >= o) incl += x;
    }
    __shared__ int ws[8];
    if (lane == 31) ws[wid] = incl;
    __syncthreads();
    int wofs = 0;
#pragma unroll
    for (int w = 0; w < 8; w++) wofs += (w < wid) ? ws[w] : 0;
    int run = bofs[z * 64 + b] + wofs + incl - tsum;
#pragma unroll
    for (int q = 0; q < 4; q++) {
        int i = base + q;
        if (i < NN) {
            rowptr[z * (NN + 1) + i] = run;
            cursor[z * NN + i] = run;
            if (i == NN - 1) rowptr[z * (NN + 1) + NN] = run + v[q];
            run += v[q];
        }
    }
}

__global__ void fillcsr(const int* __restrict__ src, const int* __restrict__ dst,
                        int* __restrict__ cursor, int* __restrict__ srcs, int n) {
    for (int i = blockIdx.x * blockDim.x + threadIdx.x; i < n; i += gridDim.x * blockDim.x) {
        int p = atomicAdd(&cursor[dst[i]], 1);
        srcs[p] = src[i];
    }
}

// ---------------- mean aggregation: one warp per dst node ----------------
__device__ __forceinline__ void f4add(float4& a, const float4 b) {
    a.x += b.x; a.y += b.y; a.z += b.z; a.w += b.w;
}

__global__ void aggregate(const float* __restrict__ xsrc, const int* __restrict__ rowptr,
                          const int* __restrict__ srcs, float* __restrict__ meanout, int n) {
    int w = (blockIdx.x * blockDim.x + threadIdx.x) >> 5;
    int lane = threadIdx.x & 31;
    if (w >= n) return;
    int beg = rowptr[w], end = rowptr[w + 1];
    float4 a0 = {0.f, 0.f, 0.f, 0.f}, a1 = a0, a2 = a0, a3 = a0;
    int e = beg;
    for (; e + 4 <= end; e += 4) {
        int s0 = srcs[e], s1 = srcs[e + 1], s2 = srcs[e + 2], s3 = srcs[e + 3];
        float4 v0 = ((const float4*)(xsrc + (size_t)s0 * C))[lane];
        float4 v1 = ((const float4*)(xsrc + (size_t)s1 * C))[lane];
        float4 v2 = ((const float4*)(xsrc + (size_t)s2 * C))[lane];
        float4 v3 = ((const float4*)(xsrc + (size_t)s3 * C))[lane];
        f4add(a0, v0); f4add(a1, v1); f4add(a2, v2); f4add(a3, v3);
    }
    for (; e < end; ++e) {
        int s = srcs[e];
        f4add(a0, ((const float4*)(xsrc + (size_t)s * C))[lane]);
    }
    f4add(a0, a1); f4add(a2, a3); f4add(a0, a2);
    int d = end - beg;
    float inv = 1.0f / (float)(d > 1 ? d : 1);
    float4 r = {a0.x * inv, a0.y * inv, a0.z * inv, a0.w * inv};
    ((float4*)(meanout + (size_t)w * C))[lane] = r;
}

// ---------------- weight prep: concat + bf16 hi/lo split ----------------
__global__ void prep_user(const float* __restrict__ Wl_iu, const float* __restrict__ b_iu, const float* __restrict__ Wr_iu,
                          const float* __restrict__ Wl_uu, const float* __restrict__ b_uu, const float* __restrict__ Wr_uu) {
    int i = blockIdx.x * blockDim.x + threadIdx.x;
    if (i < C * 384) {
        int c = i / 384, k = i - c * 384;
        float v;
        if (k < 128)      v = Wl_iu[c * 128 + k];
        else if (k < 256) v = Wl_uu[c * 128 + k - 128];
        else              v = Wr_iu[c * 128 + k - 256] + Wr_uu[c * 128 + k - 256];
        __nv_bfloat16 h = __float2bfloat16(v);
        g_Wu_hi[i] = h;
        g_Wu_lo[i] = __float2bfloat16(v - __bfloat162float(h));
        if (i < C) g_b[i] = b_iu[i] + b_uu[i];
    }
}

__global__ void prep_item(const float* __restrict__ Wl_ui, const float* __restrict__ b_ui, const float* __restrict__ Wr_ui) {
    int i = blockIdx.x * blockDim.x + threadIdx.x;
    if (i < C * 256) {
        int c = i / 256, k = i - c * 256;
        float v = (k < 128) ? Wl_ui[c * 128 + k] : Wr_ui[c * 128 + k - 128];
        __nv_bfloat16 h = __float2bfloat16(v);
        g_Wi_hi[i] = h;
        g_Wi_lo[i] = __float2bfloat16(v - __bfloat162float(h));
        if (i < C) g_b[C + i] = b_ui[i];
    }
}

// ---------------- mma.sync helpers ----------------
__device__ __forceinline__ uint32_t smem_u32(const void* p) {
    uint32_t a;
    asm("{ .reg .u64 t; cvta.to.shared.u64 t, %1; cvt.u32.u64 %0, t; }" : "=r"(a) : "l"(p));
    return a;
}

#define LDM4(r, addr) \
    asm volatile("ldmatrix.sync.aligned.m8n8.x4.shared.b16 {%0,%1,%2,%3}, [%4];" \
        : "=r"((r)[0]), "=r"((r)[1]), "=r"((r)[2]), "=r"((r)[3]) : "r"(addr))

#define MMA16816(d, a, b0, b1) \
    asm volatile("mma.sync.aligned.m16n8k16.row.col.f32.bf16.bf16.f32 " \
        "{%0,%1,%2,%3},{%4,%5,%6,%7},{%8,%9},{%0,%1,%2,%3};" \
        : "+f"((d)[0]), "+f"((d)[1]), "+f"((d)[2]), "+f"((d)[3]) \
        : "r"((a)[0]), "r"((a)[1]), "r"((a)[2]), "r"((a)[3]), "r"(b0), "r"(b1))

__device__ __forceinline__ void split2(float a, float b, uint32_t& hi, uint32_t& lo) {
    __nv_bfloat16 h0 = __float2bfloat16(a), h1 = __float2bfloat16(b);
    float r0 = a - __bfloat162float(h0), r1 = b - __bfloat162float(h1);
    __nv_bfloat16 l0 = __float2bfloat16(r0), l1 = __float2bfloat16(r1);
    hi = (uint32_t)__bfloat16_as_ushort(h0) | ((uint32_t)__bfloat16_as_ushort(h1) << 16);
    lo = (uint32_t)__bfloat16_as_ushort(l0) | ((uint32_t)__bfloat16_as_ushort(l1) << 16);
}

// ---------------- HMMA GEMM + bias + LN + ReLU ----------------
// Per CTA: 128 nodes x 128 channels. K streamed in 64-half chunks per source.
// bf16 hi/lo 3-pass: Ah*Bh + Ah*Bl + Al*Bh (fp32 accum).
// smem tiles: pitch 144 bytes (72 halves) -> conflict-free ldmatrix.
#define SA_HI 0
#define SA_LO 18432
#define SB_HI 36864
#define SB_LO 55296
#define YS_PITCH 136
#define CTRL_OFF 73728
#define SMEM_BYTES (73728 + 1536)

template <int NCH>
__global__ void __launch_bounds__(256, 1)
gemm_mma(const float* __restrict__ A0, const float* __restrict__ A1, const float* __restrict__ A2,
         const __nv_bfloat16* __restrict__ Whi, const __nv_bfloat16* __restrict__ Wlo,
         const float* __restrict__ bias, const float* __restrict__ lnw, const float* __restrict__ lnb,
         float* __restrict__ out, int n) {
    extern __shared__ __align__(16) char smp[];
    const int KTOT = NCH * 128;
    uint32_t sbase = smem_u32(smp);

    int tid = threadIdx.x, lane = tid & 31, wid = tid >> 5;
    int wr = wid >> 1, wc = wid & 1;     // warp tile: rows wr*32..+31, cols wc*64..+63
    int nodeBase = blockIdx.x * 128;

    float* sBias = (float*)(smp + CTRL_OFF);
    float* sLnw  = (float*)(smp + CTRL_OFF + 512);
    float* sLnb  = (float*)(smp + CTRL_OFF + 1024);
    if (tid < 128) { sBias[tid] = bias[tid]; sLnw[tid] = lnw[tid]; sLnb[tid] = lnb[tid]; }

    float D[2][8][4];
#pragma unroll
    for (int a = 0; a < 2; a++)
#pragma unroll
        for (int b = 0; b < 8; b++)
#pragma unroll
            for (int c = 0; c < 4; c++) D[a][b][c] = 0.f;

    const float* As[3] = {A0, A1, A2};

#pragma unroll
    for (int ch = 0; ch < NCH; ch++) {
        const float* A = As[ch];
#pragma unroll
        for (int hf = 0; hf < 2; hf++) {
            int koff = hf * 64;
            __syncthreads();   // previous iteration's ldmatrix reads done before overwrite
            // ---- A tile fill: 128 rows x 64 floats -> bf16 hi/lo ----
#pragma unroll
            for (int i = 0; i < 8; i++) {
                int j = i * 256 + tid;
                int row = j >> 4, q = j & 15;
                float4 v = make_float4(0.f, 0.f, 0.f, 0.f);
                int node = nodeBase + row;
                if (node < n) v = __ldg((const float4*)(A + (size_t)node * C + koff) + q);
                uint2 hh, ll;
                split2(v.x, v.y, hh.x, ll.x);
                split2(v.z, v.w, hh.y, ll.y);
                int off = row * 144 + q * 8;
                *(uint2*)(smp + SA_HI + off) = hh;
                *(uint2*)(smp + SA_LO + off) = ll;
            }
            // ---- B tile fill: 128 channel rows x 64 halves (pre-split bf16) ----
#pragma unroll
            for (int i = 0; i < 4; i++) {
                int j = i * 256 + tid;
                int row = j >> 3, q = j & 7;
                const uint4 vh = *(const uint4*)(Whi + (size_t)row * KTOT + ch * 128 + koff + q * 8);
                const uint4 vl = *(const uint4*)(Wlo + (size_t)row * KTOT + ch * 128 + koff + q * 8);
                int off = row * 144 + q * 16;
                *(uint4*)(smp + SB_HI + off) = vh;
                *(uint4*)(smp + SB_LO + off) = vl;
            }
            __syncthreads();
            // ---- compute: 4 k16 steps ----
#pragma unroll
            for (int s = 0; s < 4; s++) {
                uint32_t ah[2][4], al[2][4], bh[4][4], bl[4][4];
#pragma unroll
                for (int mt = 0; mt < 2; mt++) {
                    int row = wr * 32 + mt * 16 + (lane & 15);
                    int kb = s * 32 + (lane >> 4) * 16;
                    uint32_t ad = sbase + SA_HI + row * 144 + kb;
                    LDM4(ah[mt], ad);
                    LDM4(al[mt], ad + (SA_LO - SA_HI));
                }
#pragma unroll
                for (int bt = 0; bt < 4; bt++) {
                    int rown = wc * 64 + bt * 16 + ((lane >> 4) * 8 + (lane & 7));
                    int kb = s * 32 + ((lane >> 3) & 1) * 16;
                    uint32_t ad = sbase + SB_HI + rown * 144 + kb;
                    LDM4(bh[bt], ad);
                    LDM4(bl[bt], ad + (SB_LO - SB_HI));
                }
#pragma unroll
                for (int mt = 0; mt < 2; mt++)
#pragma unroll
                    for (int bt = 0; bt < 4; bt++) {
                        MMA16816(D[mt][bt * 2],     ah[mt], bh[bt][0], bh[bt][1]);
                        MMA16816(D[mt][bt * 2 + 1], ah[mt], bh[bt][2], bh[bt][3]);
                        MMA16816(D[mt][bt * 2],     ah[mt], bl[bt][0], bl[bt][1]);
                        MMA16816(D[mt][bt * 2 + 1], ah[mt], bl[bt][2], bl[bt][3]);
                        MMA16816(D[mt][bt * 2],     al[mt], bh[bt][0], bh[bt][1]);
                        MMA16816(D[mt][bt * 2 + 1], al[mt], bh[bt][2], bh[bt][3]);
                    }
            }
        }
    }

    // ---- epilogue: accum + bias -> smem, LN + ReLU, coalesced store ----
    __syncthreads();
    float* ys = (float*)smp;   // [128][YS_PITCH]
#pragma unroll
    for (int mt = 0; mt < 2; mt++) {
        int r0 = wr * 32 + mt * 16 + (lane >> 2);
#pragma unroll
        for (int bt = 0; bt < 8; bt++) {
            int nn = wc * 64 + bt * 8 + (lane & 3) * 2;
            float b0 = sBias[nn], b1 = sBias[nn + 1];
            float2 v0 = {D[mt][bt][0] + b0, D[mt][bt][1] + b1};
            float2 v1 = {D[mt][bt][2] + b0, D[mt][bt][3] + b1};
            *(float2*)&ys[r0 * YS_PITCH + nn] = v0;
            *(float2*)&ys[(r0 + 8) * YS_PITCH + nn] = v1;
        }
    }
    __syncthreads();
    if (tid < 128) {
        int row = tid;
        float s = 0.f, s2 = 0.f;
#pragma unroll
        for (int c = 0; c < 128; c++) {
            float v = ys[row * YS_PITCH + c];
            s += v; s2 += v * v;
        }
        float mu = s * (1.f / 128.f);
        float rs = rsqrtf(s2 * (1.f / 128.f) - mu * mu + 1e-5f);
#pragma unroll
        for (int c = 0; c < 128; c++) {
            float y = (ys[row * YS_PITCH + c] - mu) * rs * sLnw[c] + sLnb[c];
            ys[row * YS_PITCH + c] = fmaxf(y, 0.f);
        }
    }
    __syncthreads();
#pragma unroll 4
    for (int i = 0; i < 64; i++) {
        int j = i * 256 + tid;
        int row = j >> 7, c = j & 127;
        int node = nodeBase + row;
        if (node < n) out[(size_t)node * C + c] = ys[row * YS_PITCH + c];
    }
}

// ---------------- host launch ----------------
extern "C" void kernel_launch(void* const* d_in, const int* in_sizes, int n_in,
                              void* d_out, int out_size) {
    const float* x_user = (const float*)d_in[0];
    const float* x_item = (const float*)d_in[1];
    const int* EI[3] = {(const int*)d_in[2], (const int*)d_in[3], (const int*)d_in[4]};

    int *deg, *rowptr, *cursor, *srcs, *bsum, *bofs;
    float *agg, *xbuf, *bvec;
    __nv_bfloat16 *wuh, *wul, *wih, *wil;
    cudaGetSymbolAddress((void**)&deg, g_deg);
    cudaGetSymbolAddress((void**)&rowptr, g_rowptr);
    cudaGetSymbolAddress((void**)&cursor, g_cursor);
    cudaGetSymbolAddress((void**)&srcs, g_srcs);
    cudaGetSymbolAddress((void**)&bsum, g_bsum);
    cudaGetSymbolAddress((void**)&bofs, g_bofs);
    cudaGetSymbolAddress((void**)&agg, g_agg);
    cudaGetSymbolAddress((void**)&xbuf, g_x);
    cudaGetSymbolAddress((void**)&bvec, g_b);
    cudaGetSymbolAddress((void**)&wuh, g_Wu_hi);
    cudaGetSymbolAddress((void**)&wul, g_Wu_lo);
    cudaGetSymbolAddress((void**)&wih, g_Wi_hi);
    cudaGetSymbolAddress((void**)&wil, g_Wi_lo);

    cudaFuncSetAttribute(gemm_mma<3>, cudaFuncAttributeMaxDynamicSharedMemorySize, SMEM_BYTES);
    cudaFuncSetAttribute(gemm_mma<2>, cudaFuncAttributeMaxDynamicSharedMemorySize, SMEM_BYTES);

    float* agg_ui = agg;
    float* agg_iu = agg + (size_t)NN * C;
    float* agg_uu = agg + (size_t)2 * NN * C;
    float* xu = xbuf;
    float* xi = xbuf + (size_t)NN * C;

    // ---- CSR build (edge structure shared by both layers) ----
    zero_int<<<256, 256>>>(deg, 3 * NN);
    for (int t = 0; t < 3; t++)
        histo<<<512, 256>>>(EI[t] + NE, deg + t * NN, NE);
    scan_partial<<<dim3(NB, 3), 256>>>(deg, bsum);
    scan_bsum<<<1, 96>>>(bsum, bofs);
    scan_final<<<dim3(NB, 3), 256>>>(deg, bofs, rowptr, cursor);
    for (int t = 0; t < 3; t++)
        fillcsr<<<512, 256>>>(EI[t], EI[t] + NE, cursor + t * NN, srcs + t * NE, NE);

    const int AGG_GRID = (NN + 7) / 8;
    const int GG = (NN + 127) / 128;

    for (int layer = 0; layer < 2; layer++) {
        const float* xu_in = (layer == 0) ? x_user : xu;
        const float* xi_in = (layer == 0) ? x_item : xi;
        int pb = 5 + layer * 13;
        const float* Wl_ui = (const float*)d_in[pb + 0];
        const float* b_ui  = (const float*)d_in[pb + 1];
        const float* Wr_ui = (const float*)d_in[pb + 2];
        const float* Wl_iu = (const float*)d_in[pb + 3];
        const float* b_iu  = (const float*)d_in[pb + 4];
        const float* Wr_iu = (const float*)d_in[pb + 5];
        const float* Wl_uu = (const float*)d_in[pb + 6];
        const float* b_uu  = (const float*)d_in[pb + 7];
        const float* Wr_uu = (const float*)d_in[pb + 8];
        const float* lnw_u = (const float*)d_in[pb + 9];
        const float* lnb_u = (const float*)d_in[pb + 10];
        const float* lnw_i = (const float*)d_in[pb + 11];
        const float* lnb_i = (const float*)d_in[pb + 12];

        prep_user<<<(C * 384 + 255) / 256, 256>>>(Wl_iu, b_iu, Wr_iu, Wl_uu, b_uu, Wr_uu);
        prep_item<<<(C * 256 + 255) / 256, 256>>>(Wl_ui, b_ui, Wr_ui);

        aggregate<<<AGG_GRID, 256>>>(xu_in, rowptr + 0 * (NN + 1), srcs + 0 * NE, agg_ui, NN); // u->i
        aggregate<<<AGG_GRID, 256>>>(xi_in, rowptr + 1 * (NN + 1), srcs + 1 * NE, agg_iu, NN); // i->u
        aggregate<<<AGG_GRID, 256>>>(xu_in, rowptr + 2 * (NN + 1), srcs + 2 * NE, agg_uu, NN); // u->u

        float* out_u = (layer == 0) ? xu : ((float*)d_out);
        float* out_i = (layer == 0) ? xi : ((float*)d_out + (size_t)NN * C);
        gemm_mma<3><<<GG, 256, SMEM_BYTES>>>(agg_iu, agg_uu, xu_in, wuh, wul, bvec, lnw_u, lnb_u, out_u, NN);
        gemm_mma<2><<<GG, 256, SMEM_BYTES>>>(agg_ui, xi_in, nullptr, wih, wil, bvec + C, lnw_i, lnb_i, out_i, NN);
    }
}

// round 4
// speedup vs baseline: 3.1567x; 1.0521x over previous
#include <cuda_runtime.h>
#include <cuda_bf16.h>
#include <cstdint>

#define C   128
#define NN  50000
#define NE  600000
#define NB  49          // ceil(NN/1024)

typedef __nv_bfloat16 bf16;

// ---------------- device scratch (no allocations allowed) ----------------
__device__ __align__(16) float g_x1[2 * NN * C];          // layer-0 outputs fp32: [0]=user [1]=item
__device__ __align__(16) bf16  g_x0h[2 * NN * C];         // split of layer inputs
__device__ __align__(16) bf16  g_x0l[2 * NN * C];
__device__ __align__(16) bf16  g_x1h[2 * NN * C];         // split of layer-0 outputs
__device__ __align__(16) bf16  g_x1l[2 * NN * C];
__device__ __align__(16) bf16  g_aggh[2][3 * NN * C];     // [layer][type]: 0 ui, 1 iu, 2 uu
__device__ __align__(16) bf16  g_aggl[2][3 * NN * C];
__device__ __align__(16) bf16  g_Wuh[2][C * 384];
__device__ __align__(16) bf16  g_Wul[2][C * 384];
__device__ __align__(16) bf16  g_Wih[2][C * 256];
__device__ __align__(16) bf16  g_Wil[2][C * 256];
__device__ float g_b[2][2 * C];
__device__ int   g_deg[3 * NN];
__device__ int   g_rowptr[3 * (NN + 1)];
__device__ int   g_cursor[3 * NN];
__device__ int   g_srcs[3 * NE];
__device__ int   g_bsum[3 * 64];
__device__ int   g_bofs[3 * 64];

// ---------------- CSR build ----------------
__global__ void zero_int(int* p, int n) {
    for (int i = blockIdx.x * blockDim.x + threadIdx.x; i < n; i += gridDim.x * blockDim.x) p[i] = 0;
}

__global__ void histo(const int* __restrict__ dst, int* __restrict__ deg, int n) {
    for (int i = blockIdx.x * blockDim.x + threadIdx.x; i < n; i += gridDim.x * blockDim.x)
        atomicAdd(&deg[dst[i]], 1);
}

__global__ void scan_partial(const int* __restrict__ deg, int* __restrict__ bsum) {
    int z = blockIdx.y, b = blockIdx.x, t = threadIdx.x;
    int lane = t & 31, wid = t >> 5;
    int s = 0;
#pragma unroll
    for (int q = 0; q < 4; q++) {
        int i = b * 1024 + q * 256 + t;
        if (i < NN) s += deg[z * NN + i];
    }
    for (int o = 16; o; o >>= 1) s += __shfl_down_sync(0xffffffffu, s, o);
    __shared__ int ws[8];
    if (lane == 0) ws[wid] = s;
    __syncthreads();
    if (t == 0) {
        int tot = 0;
#pragma unroll
        for (int w = 0; w < 8; w++) tot += ws[w];
        bsum[z * 64 + b] = tot;
    }
}

__global__ void scan_bsum(const int* __restrict__ bsum, int* __restrict__ bofs) {
    int t = threadIdx.x;
    int z = t >> 5, lane = t & 31;
    if (z < 3) {
        int carry = 0;
        for (int bb = 0; bb < 64; bb += 32) {
            int idx = bb + lane;
            int v = (idx < NB) ? bsum[z * 64 + idx] : 0;
            int incl = v;
            for (int o = 1; o < 32; o <<= 1) {
                int x = __shfl_up_sync(0xffffffffu, incl, o);
                if (lane >= o) incl += x;
            }
            bofs[z * 64 + idx] = carry + incl - v;
            carry += __shfl_sync(0xffffffffu, incl, 31);
        }
    }
}

__global__ void scan_final(const int* __restrict__ deg, const int* __restrict__ bofs,
                           int* __restrict__ rowptr, int* __restrict__ cursor) {
    int z = blockIdx.y, b = blockIdx.x, t = threadIdx.x;
    int lane = t & 31, wid = t >> 5;
    int base = b * 1024 + t * 4;
    int v[4]; int tsum = 0;
#pragma unroll
    for (int q = 0; q < 4; q++) {
        int i = base + q;
        v[q] = (i < NN) ? deg[z * NN + i] : 0;
        tsum += v[q];
    }
    int incl = tsum;
    for (int o = 1; o < 32; o <<= 1) {
        int x = __shfl_up_sync(0xffffffffu, incl, o);
        if (lane >= o) incl += x;
    }
    __shared__ int ws[8];
    if (lane == 31) ws[wid] = incl;
    __syncthreads();
    int wofs = 0;
#pragma unroll
    for (int w = 0; w < 8; w++) wofs += (w < wid) ? ws[w] : 0;
    int run = bofs[z * 64 + b] + wofs + incl - tsum;
#pragma unroll
    for (int q = 0; q < 4; q++) {
        int i = base + q;
        if (i < NN) {
            rowptr[z * (NN + 1) + i] = run;
            cursor[z * NN + i] = run;
            if (i == NN - 1) rowptr[z * (NN + 1) + NN] = run + v[q];
            run += v[q];
        }
    }
}

__global__ void fillcsr(const int* __restrict__ src, const int* __restrict__ dst,
                        int* __restrict__ cursor, int* __restrict__ srcs, int n) {
    for (int i = blockIdx.x * blockDim.x + threadIdx.x; i < n; i += gridDim.x * blockDim.x) {
        int p = atomicAdd(&cursor[dst[i]], 1);
        srcs[p] = src[i];
    }
}

// ---------------- bf16 split helpers ----------------
__device__ __forceinline__ void split2(float a, float b, uint32_t& hi, uint32_t& lo) {
    bf16 h0 = __float2bfloat16(a), h1 = __float2bfloat16(b);
    float r0 = a - __bfloat162float(h0), r1 = b - __bfloat162float(h1);
    bf16 l0 = __float2bfloat16(r0), l1 = __float2bfloat16(r1);
    hi = (uint32_t)__bfloat16_as_ushort(h0) | ((uint32_t)__bfloat16_as_ushort(h1) << 16);
    lo = (uint32_t)__bfloat16_as_ushort(l0) | ((uint32_t)__bfloat16_as_ushort(l1) << 16);
}

// split fp32 features into bf16 hi/lo
__global__ void split_x(const float* __restrict__ x, bf16* __restrict__ xh, bf16* __restrict__ xl, int n4) {
    for (int i = blockIdx.x * blockDim.x + threadIdx.x; i < n4; i += gridDim.x * blockDim.x) {
        float4 v = ((const float4*)x)[i];
        uint2 h, l;
        split2(v.x, v.y, h.x, l.x);
        split2(v.z, v.w, h.y, l.y);
        ((uint2*)xh)[i] = h;
        ((uint2*)xl)[i] = l;
    }
}

// ---------------- mean aggregation: one warp per dst node, bf16 hi/lo output ----------------
__device__ __forceinline__ void f4add(float4& a, const float4 b) {
    a.x += b.x; a.y += b.y; a.z += b.z; a.w += b.w;
}

__global__ void aggregate(const float* __restrict__ xsrc, const int* __restrict__ rowptr,
                          const int* __restrict__ srcs,
                          bf16* __restrict__ aggh, bf16* __restrict__ aggl, int n) {
    int w = (blockIdx.x * blockDim.x + threadIdx.x) >> 5;
    int lane = threadIdx.x & 31;
    if (w >= n) return;
    int beg = rowptr[w], end = rowptr[w + 1];
    float4 a0 = {0.f, 0.f, 0.f, 0.f}, a1 = a0, a2 = a0, a3 = a0;
    int e = beg;
    for (; e + 4 <= end; e += 4) {
        int s0 = srcs[e], s1 = srcs[e + 1], s2 = srcs[e + 2], s3 = srcs[e + 3];
        float4 v0 = ((const float4*)(xsrc + (size_t)s0 * C))[lane];
        float4 v1 = ((const float4*)(xsrc + (size_t)s1 * C))[lane];
        float4 v2 = ((const float4*)(xsrc + (size_t)s2 * C))[lane];
        float4 v3 = ((const float4*)(xsrc + (size_t)s3 * C))[lane];
        f4add(a0, v0); f4add(a1, v1); f4add(a2, v2); f4add(a3, v3);
    }
    for (; e < end; ++e) {
        int s = srcs[e];
        f4add(a0, ((const float4*)(xsrc + (size_t)s * C))[lane]);
    }
    f4add(a0, a1); f4add(a2, a3); f4add(a0, a2);
    int d = end - beg;
    float inv = 1.0f / (float)(d > 1 ? d : 1);
    float4 r = {a0.x * inv, a0.y * inv, a0.z * inv, a0.w * inv};
    uint2 h, l;
    split2(r.x, r.y, h.x, l.x);
    split2(r.z, r.w, h.y, l.y);
    *(uint2*)(aggh + (size_t)w * C + lane * 4) = h;
    *(uint2*)(aggl + (size_t)w * C + lane * 4) = l;
}

// ---------------- weight prep: concat + bf16 hi/lo split ----------------
__global__ void prep_user(const float* __restrict__ Wl_iu, const float* __restrict__ b_iu, const float* __restrict__ Wr_iu,
                          const float* __restrict__ Wl_uu, const float* __restrict__ b_uu, const float* __restrict__ Wr_uu,
                          bf16* __restrict__ Wh, bf16* __restrict__ Wl, float* __restrict__ bv) {
    int i = blockIdx.x * blockDim.x + threadIdx.x;
    if (i < C * 384) {
        int c = i / 384, k = i - c * 384;
        float v;
        if (k < 128)      v = Wl_iu[c * 128 + k];
        else if (k < 256) v = Wl_uu[c * 128 + k - 128];
        else              v = Wr_iu[c * 128 + k - 256] + Wr_uu[c * 128 + k - 256];
        bf16 h = __float2bfloat16(v);
        Wh[i] = h;
        Wl[i] = __float2bfloat16(v - __bfloat162float(h));
        if (i < C) bv[i] = b_iu[i] + b_uu[i];
    }
}

__global__ void prep_item(const float* __restrict__ Wl_ui, const float* __restrict__ b_ui, const float* __restrict__ Wr_ui,
                          bf16* __restrict__ Wh, bf16* __restrict__ Wl, float* __restrict__ bv) {
    int i = blockIdx.x * blockDim.x + threadIdx.x;
    if (i < C * 256) {
        int c = i / 256, k = i - c * 256;
        float v = (k < 128) ? Wl_ui[c * 128 + k] : Wr_ui[c * 128 + k - 128];
        bf16 h = __float2bfloat16(v);
        Wh[i] = h;
        Wl[i] = __float2bfloat16(v - __bfloat162float(h));
        if (i < C) bv[i] = b_ui[i];
    }
}

// ---------------- mma.sync helpers ----------------
__device__ __forceinline__ uint32_t smem_u32(const void* p) {
    uint32_t a;
    asm("{ .reg .u64 t; cvta.to.shared.u64 t, %1; cvt.u32.u64 %0, t; }" : "=r"(a) : "l"(p));
    return a;
}

#define LDM4(r, addr) \
    asm volatile("ldmatrix.sync.aligned.m8n8.x4.shared.b16 {%0,%1,%2,%3}, [%4];" \
        : "=r"((r)[0]), "=r"((r)[1]), "=r"((r)[2]), "=r"((r)[3]) : "r"(addr))

#define MMA16816(d, a, b0, b1) \
    asm volatile("mma.sync.aligned.m16n8k16.row.col.f32.bf16.bf16.f32 " \
        "{%0,%1,%2,%3},{%4,%5,%6,%7},{%8,%9},{%0,%1,%2,%3};" \
        : "+f"((d)[0]), "+f"((d)[1]), "+f"((d)[2]), "+f"((d)[3]) \
        : "r"((a)[0]), "r"((a)[1]), "r"((a)[2]), "r"((a)[3]), "r"(b0), "r"(b1))

__device__ __forceinline__ void cp16(uint32_t dst, const void* src, bool pred) {
    int sz = pred ? 16 : 0;
    asm volatile("cp.async.cg.shared.global [%0], [%1], 16, %2;" :: "r"(dst), "l"(src), "r"(sz));
}
__device__ __forceinline__ void cp_commit() { asm volatile("cp.async.commit_group;"); }
__device__ __forceinline__ void cp_wait1() { asm volatile("cp.async.wait_group 1;"); }

// ---------------- cp.async double-buffered HMMA GEMM + bias + LN + ReLU ----------------
// Per CTA: 128 nodes x 128 channels. K streamed in 64-half chunks, all operands pre-split bf16.
#define BUF_STRIDE 73728
#define SA_HI 0
#define SA_LO 18432
#define SB_HI 36864
#define SB_LO 55296
#define CTRL_OFF 147456
#define YS_PITCH 136
#define SMEM_BYTES (147456 + 1536)

template <int NCH>
__global__ void __launch_bounds__(256, 1)
gemm_mma(const bf16* __restrict__ Ah0, const bf16* __restrict__ Al0,
         const bf16* __restrict__ Ah1, const bf16* __restrict__ Al1,
         const bf16* __restrict__ Ah2, const bf16* __restrict__ Al2,
         const bf16* __restrict__ Whi, const bf16* __restrict__ Wlo,
         const float* __restrict__ bias, const float* __restrict__ lnw, const float* __restrict__ lnb,
         float* __restrict__ out, bf16* __restrict__ outh, bf16* __restrict__ outl, int n) {
    extern __shared__ __align__(16) char smp[];
    const int KTOT = NCH * 128;
    const int NC2 = NCH * 2;
    uint32_t sbase = smem_u32(smp);

    int tid = threadIdx.x, lane = tid & 31, wid = tid >> 5;
    int wr = wid >> 1, wc = wid & 1;
    int nodeBase = blockIdx.x * 128;

    float* sBias = (float*)(smp + CTRL_OFF);
    float* sLnw  = (float*)(smp + CTRL_OFF + 512);
    float* sLnb  = (float*)(smp + CTRL_OFF + 1024);
    if (tid < 128) { sBias[tid] = bias[tid]; sLnw[tid] = lnw[tid]; sLnb[tid] = lnb[tid]; }

    const bf16* AH[3] = {Ah0, Ah1, Ah2};
    const bf16* AL[3] = {Al0, Al1, Al2};

    // per-thread cp.async coordinates (fixed across chunks)
    // A tiles: 1024 x 16B each; rowA = j>>3, qA = j&7
    // B tiles: same geometry over channel rows
    float D[2][8][4];
#pragma unroll
    for (int a = 0; a < 2; a++)
#pragma unroll
        for (int b = 0; b < 8; b++)
#pragma unroll
            for (int c = 0; c < 4; c++) D[a][b][c] = 0.f;

    auto load_chunk = [&](int c2, int buf) {
        int srcIdx = c2 >> 1;
        int koff = (c2 & 1) * 64;
        const bf16* Ah = AH[srcIdx];
        const bf16* Al = AL[srcIdx];
        uint32_t bb = sbase + buf * BUF_STRIDE;
#pragma unroll
        for (int i = 0; i < 4; i++) {
            int j = i * 256 + tid;
            int row = j >> 3, q = j & 7;
            int node = nodeBase + row;
            bool ok = node < n;
            size_t ga = (size_t)(ok ? node : 0) * C + koff + q * 8;
            uint32_t off = row * 144 + q * 16;
            cp16(bb + SA_HI + off, Ah + ga, ok);
            cp16(bb + SA_LO + off, Al + ga, ok);
        }
#pragma unroll
        for (int i = 0; i < 4; i++) {
            int j = i * 256 + tid;
            int row = j >> 3, q = j & 7;
            size_t ga = (size_t)row * KTOT + c2 * 64 + q * 8;
            uint32_t off = row * 144 + q * 16;
            cp16(bb + SB_HI + off, Whi + ga, true);
            cp16(bb + SB_LO + off, Wlo + ga, true);
        }
    };

    // prologue
    load_chunk(0, 0);
    cp_commit();

#pragma unroll
    for (int c2 = 0; c2 < NC2; c2++) {
        if (c2 + 1 < NC2) load_chunk(c2 + 1, (c2 + 1) & 1);
        cp_commit();
        cp_wait1();
        __syncthreads();
        uint32_t bb = sbase + (c2 & 1) * BUF_STRIDE;
        // ---- compute: 4 k16 steps over this 64-half chunk ----
#pragma unroll
        for (int s = 0; s < 4; s++) {
            uint32_t ah[2][4], al[2][4], bh[4][4], bl[4][4];
#pragma unroll
            for (int mt = 0; mt < 2; mt++) {
                int row = wr * 32 + mt * 16 + (lane & 15);
                int kb = s * 32 + (lane >> 4) * 16;
                uint32_t ad = bb + SA_HI + row * 144 + kb;
                LDM4(ah[mt], ad);
                LDM4(al[mt], ad + (SA_LO - SA_HI));
            }
#pragma unroll
            for (int bt = 0; bt < 4; bt++) {
                int rown = wc * 64 + bt * 16 + ((lane >> 4) * 8 + (lane & 7));
                int kb = s * 32 + ((lane >> 3) & 1) * 16;
                uint32_t ad = bb + SB_HI + rown * 144 + kb;
                LDM4(bh[bt], ad);
                LDM4(bl[bt], ad + (SB_LO - SB_HI));
            }
#pragma unroll
            for (int mt = 0; mt < 2; mt++)
#pragma unroll
                for (int bt = 0; bt < 4; bt++) {
                    MMA16816(D[mt][bt * 2],     ah[mt], bh[bt][0], bh[bt][1]);
                    MMA16816(D[mt][bt * 2 + 1], ah[mt], bh[bt][2], bh[bt][3]);
                    MMA16816(D[mt][bt * 2],     ah[mt], bl[bt][0], bl[bt][1]);
                    MMA16816(D[mt][bt * 2 + 1], ah[mt], bl[bt][2], bl[bt][3]);
                    MMA16816(D[mt][bt * 2],     al[mt], bh[bt][0], bh[bt][1]);
                    MMA16816(D[mt][bt * 2 + 1], al[mt], bh[bt][2], bh[bt][3]);
                }
        }
        __syncthreads();
    }

    // ---- epilogue: accum + bias -> smem, LN + ReLU, stores (+ optional bf16 hi/lo) ----
    float* ys = (float*)smp;   // [128][YS_PITCH]
#pragma unroll
    for (int mt = 0; mt < 2; mt++) {
        int r0 = wr * 32 + mt * 16 + (lane >> 2);
#pragma unroll
        for (int bt = 0; bt < 8; bt++) {
            int nn = wc * 64 + bt * 8 + (lane & 3) * 2;
            float b0 = sBias[nn], b1 = sBias[nn + 1];
            float2 v0 = {D[mt][bt][0] + b0, D[mt][bt][1] + b1};
            float2 v1 = {D[mt][bt][2] + b0, D[mt][bt][3] + b1};
            *(float2*)&ys[r0 * YS_PITCH + nn] = v0;
            *(float2*)&ys[(r0 + 8) * YS_PITCH + nn] = v1;
        }
    }
    __syncthreads();
    if (tid < 128) {
        int row = tid;
        float s = 0.f, s2 = 0.f;
#pragma unroll
        for (int c = 0; c < 128; c++) {
            float v = ys[row * YS_PITCH + c];
            s += v; s2 += v * v;
        }
        float mu = s * (1.f / 128.f);
        float rs = rsqrtf(s2 * (1.f / 128.f) - mu * mu + 1e-5f);
#pragma unroll
        for (int c = 0; c < 128; c++) {
            float y = (ys[row * YS_PITCH + c] - mu) * rs * sLnw[c] + sLnb[c];
            ys[row * YS_PITCH + c] = fmaxf(y, 0.f);
        }
    }
    __syncthreads();
#pragma unroll 4
    for (int i = 0; i < 32; i++) {
        int j = i * 256 + tid;           // 8192 float2 slots
        int row = j >> 6, cp = (j & 63) * 2;
        int node = nodeBase + row;
        if (node < n) {
            float v0 = ys[row * YS_PITCH + cp];
            float v1 = ys[row * YS_PITCH + cp + 1];
            *(float2*)(out + (size_t)node * C + cp) = make_float2(v0, v1);
            if (outh) {
                uint32_t h, l;
                split2(v0, v1, h, l);
                *(uint32_t*)(outh + (size_t)node * C + cp) = h;
                *(uint32_t*)(outl + (size_t)node * C + cp) = l;
            }
        }
    }
}

// ---------------- host launch ----------------
extern "C" void kernel_launch(void* const* d_in, const int* in_sizes, int n_in,
                              void* d_out, int out_size) {
    const float* x_user = (const float*)d_in[0];
    const float* x_item = (const float*)d_in[1];
    const int* EI[3] = {(const int*)d_in[2], (const int*)d_in[3], (const int*)d_in[4]};

    int *deg, *rowptr, *cursor, *srcs, *bsum, *bofs;
    float *x1, *bv;
    bf16 *x0h, *x0l, *x1h, *x1l, *aggh, *aggl, *wuh, *wul, *wih, *wil;
    cudaGetSymbolAddress((void**)&deg, g_deg);
    cudaGetSymbolAddress((void**)&rowptr, g_rowptr);
    cudaGetSymbolAddress((void**)&cursor, g_cursor);
    cudaGetSymbolAddress((void**)&srcs, g_srcs);
    cudaGetSymbolAddress((void**)&bsum, g_bsum);
    cudaGetSymbolAddress((void**)&bofs, g_bofs);
    cudaGetSymbolAddress((void**)&x1, g_x1);
    cudaGetSymbolAddress((void**)&x0h, g_x0h);
    cudaGetSymbolAddress((void**)&x0l, g_x0l);
    cudaGetSymbolAddress((void**)&x1h, g_x1h);
    cudaGetSymbolAddress((void**)&x1l, g_x1l);
    cudaGetSymbolAddress((void**)&aggh, g_aggh);
    cudaGetSymbolAddress((void**)&aggl, g_aggl);
    cudaGetSymbolAddress((void**)&bv, g_b);
    cudaGetSymbolAddress((void**)&wuh, g_Wuh);
    cudaGetSymbolAddress((void**)&wul, g_Wul);
    cudaGetSymbolAddress((void**)&wih, g_Wih);
    cudaGetSymbolAddress((void**)&wil, g_Wil);

    cudaFuncSetAttribute(gemm_mma<3>, cudaFuncAttributeMaxDynamicSharedMemorySize, SMEM_BYTES);
    cudaFuncSetAttribute(gemm_mma<2>, cudaFuncAttributeMaxDynamicSharedMemorySize, SMEM_BYTES);

    const size_t NC = (size_t)NN * C;
    // per-layer agg buffers (double-buffered for cross-stream safety)
    bf16* Ah[2][3]; bf16* Al[2][3];
    for (int L = 0; L < 2; L++)
        for (int t = 0; t < 3; t++) {
            Ah[L][t] = aggh + (size_t)L * 3 * NC + (size_t)t * NC;
            Al[L][t] = aggl + (size_t)L * 3 * NC + (size_t)t * NC;
        }
    float* xu1 = x1;            // layer-0 user out fp32
    float* xi1 = x1 + NC;       // layer-0 item out fp32

    cudaStream_t s2;
    cudaStreamCreateWithFlags(&s2, cudaStreamNonBlocking);
    cudaEvent_t evA, evB, evD, evE;
    cudaEventCreateWithFlags(&evA, cudaEventDisableTiming);
    cudaEventCreateWithFlags(&evB, cudaEventDisableTiming);
    cudaEventCreateWithFlags(&evD, cudaEventDisableTiming);
    cudaEventCreateWithFlags(&evE, cudaEventDisableTiming);

    // ---- setup: CSR + weight prep + input splits (main stream) ----
    zero_int<<<256, 256>>>(deg, 3 * NN);
    for (int t = 0; t < 3; t++)
        histo<<<512, 256>>>(EI[t] + NE, deg + t * NN, NE);
    scan_partial<<<dim3(NB, 3), 256>>>(deg, bsum);
    scan_bsum<<<1, 96>>>(bsum, bofs);
    scan_final<<<dim3(NB, 3), 256>>>(deg, bofs, rowptr, cursor);
    for (int t = 0; t < 3; t++)
        fillcsr<<<512, 256>>>(EI[t], EI[t] + NE, cursor + t * NN, srcs + t * NE, NE);

    for (int L = 0; L < 2; L++) {
        int pb = 5 + L * 13;
        prep_user<<<(C * 384 + 255) / 256, 256>>>((const float*)d_in[pb + 3], (const float*)d_in[pb + 4], (const float*)d_in[pb + 5],
                                                  (const float*)d_in[pb + 6], (const float*)d_in[pb + 7], (const float*)d_in[pb + 8],
                                                  wuh + (size_t)L * C * 384, wul + (size_t)L * C * 384, bv + L * 2 * C);
        prep_item<<<(C * 256 + 255) / 256, 256>>>((const float*)d_in[pb + 0], (const float*)d_in[pb + 1], (const float*)d_in[pb + 2],
                                                  wih + (size_t)L * C * 256, wil + (size_t)L * C * 256, bv + L * 2 * C + C);
    }
    split_x<<<512, 256>>>(x_user, x0h, x0l, NC / 4);
    split_x<<<512, 256>>>(x_item, x0h + NC, x0l + NC, NC / 4);

    const int AGG_GRID = (NN + 7) / 8;
    const int GG = (NN + 127) / 128;

    const float* lnw[2][2], *lnb[2][2];
    for (int L = 0; L < 2; L++) {
        int pb = 5 + L * 13;
        lnw[L][0] = (const float*)d_in[pb + 9];  lnb[L][0] = (const float*)d_in[pb + 10];  // user
        lnw[L][1] = (const float*)d_in[pb + 11]; lnb[L][1] = (const float*)d_in[pb + 12];  // item
    }

    // ======== layer 0 ========
    aggregate<<<AGG_GRID, 256>>>(x_user, rowptr + 0 * (NN + 1), srcs + 0 * NE, Ah[0][0], Al[0][0], NN); // u->i
    cudaEventRecord(evA, 0);
    aggregate<<<AGG_GRID, 256>>>(x_item, rowptr + 1 * (NN + 1), srcs + 1 * NE, Ah[0][1], Al[0][1], NN); // i->u
    aggregate<<<AGG_GRID, 256>>>(x_user, rowptr + 2 * (NN + 1), srcs + 2 * NE, Ah[0][2], Al[0][2], NN); // u->u

    // item GEMM L0 on s2 (needs only agg_ui + x_item splits + prep)
    cudaStreamWaitEvent(s2, evA, 0);
    gemm_mma<2><<<GG, 256, SMEM_BYTES, s2>>>(Ah[0][0], Al[0][0], x0h + NC, x0l + NC, nullptr, nullptr,
                                             wih, wil, bv + C, lnw[0][1], lnb[0][1],
                                             xi1, x1h + NC, x1l + NC, NN);
    cudaEventRecord(evB, s2);

    // user GEMM L0 on main
    gemm_mma<3><<<GG, 256, SMEM_BYTES>>>(Ah[0][1], Al[0][1], Ah[0][2], Al[0][2], x0h, x0l,
                                         wuh, wul, bv, lnw[0][0], lnb[0][0],
                                         xu1, x1h, x1l, NN);

    // ======== layer 1 ========
    aggregate<<<AGG_GRID, 256>>>(xu1, rowptr + 0 * (NN + 1), srcs + 0 * NE, Ah[1][0], Al[1][0], NN); // u->i
    cudaEventRecord(evD, 0);
    aggregate<<<AGG_GRID, 256>>>(xu1, rowptr + 2 * (NN + 1), srcs + 2 * NE, Ah[1][2], Al[1][2], NN); // u->u
    cudaStreamWaitEvent(0, evB, 0);
    aggregate<<<AGG_GRID, 256>>>(xi1, rowptr + 1 * (NN + 1), srcs + 1 * NE, Ah[1][1], Al[1][1], NN); // i->u

    // item GEMM L1 on s2 -> d_out second half
    cudaStreamWaitEvent(s2, evD, 0);
    gemm_mma<2><<<GG, 256, SMEM_BYTES, s2>>>(Ah[1][0], Al[1][0], x1h + NC, x1l + NC, nullptr, nullptr,
                                             wih + (size_t)C * 256, wil + (size_t)C * 256, bv + 2 * C + C,
                                             lnw[1][1], lnb[1][1],
                                             (float*)d_out + NC, nullptr, nullptr, NN);
    cudaEventRecord(evE, s2);

    // user GEMM L1 on main -> d_out first half
    gemm_mma<3><<<GG, 256, SMEM_BYTES>>>(Ah[1][1], Al[1][1], Ah[1][2], Al[1][2], x1h, x1l,
                                         wuh + (size_t)C * 384, wul + (size_t)C * 384, bv + 2 * C,
                                         lnw[1][0], lnb[1][0],
                                         (float*)d_out, nullptr, nullptr, NN);
    cudaStreamWaitEvent(0, evE, 0);
}

// round 5
// speedup vs baseline: 3.6317x; 1.1505x over previous
#include <cuda_runtime.h>
#include <cuda_bf16.h>
#include <cuda_fp16.h>
#include <cstdint>

#define C   128
#define NN  50000
#define NE  600000
#define NB  49          // ceil(NN/1024)

typedef __nv_bfloat16 bf16;

// ---------------- device scratch (no allocations allowed) ----------------
__device__ __align__(16) bf16   g_x0h[2 * NN * C];        // bf16 hi/lo splits of layer-0 inputs
__device__ __align__(16) bf16   g_x0l[2 * NN * C];
__device__ __align__(16) bf16   g_x1h[2 * NN * C];        // splits of layer-0 outputs
__device__ __align__(16) bf16   g_x1l[2 * NN * C];
__device__ __align__(16) __half g_x0f[2 * NN * C];        // fp16 gather copies
__device__ __align__(16) __half g_x1f[2 * NN * C];
__device__ __align__(16) bf16   g_aggh[2][3 * NN * C];    // [layer][type]: 0 ui, 1 iu, 2 uu
__device__ __align__(16) bf16   g_aggl[2][3 * NN * C];
__device__ __align__(16) bf16   g_Wuh[2][C * 384];
__device__ __align__(16) bf16   g_Wul[2][C * 384];
__device__ __align__(16) bf16   g_Wih[2][C * 256];
__device__ __align__(16) bf16   g_Wil[2][C * 256];
__device__ float g_b[2][2 * C];
__device__ int   g_deg[3 * NN];
__device__ int   g_rowptr[3 * (NN + 1)];
__device__ int   g_cursor[3 * NN];
__device__ int   g_srcs[3 * NE];
__device__ int   g_bsum[3 * 64];
__device__ int   g_bofs[3 * 64];

// ---------------- CSR build ----------------
__global__ void zero_int(int* p, int n) {
    for (int i = blockIdx.x * blockDim.x + threadIdx.x; i < n; i += gridDim.x * blockDim.x) p[i] = 0;
}

__global__ void histo3(const int* __restrict__ e0, const int* __restrict__ e1, const int* __restrict__ e2,
                       int* __restrict__ deg) {
    int z = blockIdx.y;
    const int* dst = (z == 0 ? e0 : (z == 1 ? e1 : e2)) + NE;
    int* dg = deg + z * NN;
    for (int i = blockIdx.x * blockDim.x + threadIdx.x; i < NE; i += gridDim.x * blockDim.x)
        atomicAdd(&dg[dst[i]], 1);
}

__global__ void scan_partial(const int* __restrict__ deg, int* __restrict__ bsum) {
    int z = blockIdx.y, b = blockIdx.x, t = threadIdx.x;
    int lane = t & 31, wid = t >> 5;
    int s = 0;
#pragma unroll
    for (int q = 0; q < 4; q++) {
        int i = b * 1024 + q * 256 + t;
        if (i < NN) s += deg[z * NN + i];
    }
    for (int o = 16; o; o >>= 1) s += __shfl_down_sync(0xffffffffu, s, o);
    __shared__ int ws[8];
    if (lane == 0) ws[wid] = s;
    __syncthreads();
    if (t == 0) {
        int tot = 0;
#pragma unroll
        for (int w = 0; w < 8; w++) tot += ws[w];
        bsum[z * 64 + b] = tot;
    }
}

__global__ void scan_bsum(const int* __restrict__ bsum, int* __restrict__ bofs) {
    int t = threadIdx.x;
    int z = t >> 5, lane = t & 31;
    if (z < 3) {
        int carry = 0;
        for (int bb = 0; bb < 64; bb += 32) {
            int idx = bb + lane;
            int v = (idx < NB) ? bsum[z * 64 + idx] : 0;
            int incl = v;
            for (int o = 1; o < 32; o <<= 1) {
                int x = __shfl_up_sync(0xffffffffu, incl, o);
                if (lane >= o) incl += x;
            }
            bofs[z * 64 + idx] = carry + incl - v;
            carry += __shfl_sync(0xffffffffu, incl, 31);
        }
    }
}

__global__ void scan_final(const int* __restrict__ deg, const int* __restrict__ bofs,
                           int* __restrict__ rowptr, int* __restrict__ cursor) {
    int z = blockIdx.y, b = blockIdx.x, t = threadIdx.x;
    int lane = t & 31, wid = t >> 5;
    int base = b * 1024 + t * 4;
    int v[4]; int tsum = 0;
#pragma unroll
    for (int q = 0; q < 4; q++) {
        int i = base + q;
        v[q] = (i < NN) ? deg[z * NN + i] : 0;
        tsum += v[q];
    }
    int incl = tsum;
    for (int o = 1; o < 32; o <<= 1) {
        int x = __shfl_up_sync(0xffffffffu, incl, o);
        if (lane >= o) incl += x;
    }
    __shared__ int ws[8];
    if (lane == 31) ws[wid] = incl;
    __syncthreads();
    int wofs = 0;
#pragma unroll
    for (int w = 0; w < 8; w++) wofs += (w < wid) ? ws[w] : 0;
    int run = bofs[z * 64 + b] + wofs + incl - tsum;
#pragma unroll
    for (int q = 0; q < 4; q++) {
        int i = base + q;
        if (i < NN) {
            rowptr[z * (NN + 1) + i] = run;
            cursor[z * NN + i] = run;
            if (i == NN - 1) rowptr[z * (NN + 1) + NN] = run + v[q];
            run += v[q];
        }
    }
}

__global__ void fillcsr3(const int* __restrict__ e0, const int* __restrict__ e1, const int* __restrict__ e2,
                         int* __restrict__ cursor, int* __restrict__ srcs) {
    int z = blockIdx.y;
    const int* base = (z == 0 ? e0 : (z == 1 ? e1 : e2));
    const int* src = base;
    const int* dst = base + NE;
    int* cur = cursor + z * NN;
    int* out = srcs + z * NE;
    for (int i = blockIdx.x * blockDim.x + threadIdx.x; i < NE; i += gridDim.x * blockDim.x) {
        int p = atomicAdd(&cur[dst[i]], 1);
        out[p] = src[i];
    }
}

// ---------------- bf16 split helpers ----------------
__device__ __forceinline__ void split2(float a, float b, uint32_t& hi, uint32_t& lo) {
    bf16 h0 = __float2bfloat16(a), h1 = __float2bfloat16(b);
    float r0 = a - __bfloat162float(h0), r1 = b - __bfloat162float(h1);
    bf16 l0 = __float2bfloat16(r0), l1 = __float2bfloat16(r1);
    hi = (uint32_t)__bfloat16_as_ushort(h0) | ((uint32_t)__bfloat16_as_ushort(h1) << 16);
    lo = (uint32_t)__bfloat16_as_ushort(l0) | ((uint32_t)__bfloat16_as_ushort(l1) << 16);
}

// split fp32 features into bf16 hi/lo + fp16 copy; y selects user/item
__global__ void split_x(const float* __restrict__ xu, const float* __restrict__ xi,
                        bf16* __restrict__ xh, bf16* __restrict__ xl, __half* __restrict__ xf) {
    const size_t NC = (size_t)NN * C;
    int y = blockIdx.y;
    const float* x = y ? xi : xu;
    bf16* oh = xh + y * NC;
    bf16* ol = xl + y * NC;
    __half* of = xf + y * NC;
    int n4 = NC / 4;
    for (int i = blockIdx.x * blockDim.x + threadIdx.x; i < n4; i += gridDim.x * blockDim.x) {
        float4 v = ((const float4*)x)[i];
        uint2 h, l;
        split2(v.x, v.y, h.x, l.x);
        split2(v.z, v.w, h.y, l.y);
        ((uint2*)oh)[i] = h;
        ((uint2*)ol)[i] = l;
        __half2 f0 = __floats2half2_rn(v.x, v.y);
        __half2 f1 = __floats2half2_rn(v.z, v.w);
        uint2 fp; fp.x = *(uint32_t*)&f0; fp.y = *(uint32_t*)&f1;
        ((uint2*)of)[i] = fp;
    }
}

// ---------------- mean aggregation (fp16 gather), 3 types in one launch ----------------
__device__ __forceinline__ float4 h2f4(uint2 v) {
    __half2 p0 = *(__half2*)&v.x, p1 = *(__half2*)&v.y;
    float2 f0 = __half22float2(p0), f1 = __half22float2(p1);
    return make_float4(f0.x, f0.y, f1.x, f1.y);
}
__device__ __forceinline__ void f4add(float4& a, const float4 b) {
    a.x += b.x; a.y += b.y; a.z += b.z; a.w += b.w;
}

__global__ void agg3(const __half* __restrict__ xu16, const __half* __restrict__ xi16,
                     const int* __restrict__ rowptr, const int* __restrict__ srcs,
                     bf16* __restrict__ aggh, bf16* __restrict__ aggl) {
    const size_t NC = (size_t)NN * C;
    int z = blockIdx.y;
    const __half* xsrc = (z == 1) ? xi16 : xu16;
    const int* rp = rowptr + z * (NN + 1);
    const int* ss = srcs + z * NE;
    bf16* oh = aggh + z * NC;
    bf16* ol = aggl + z * NC;

    int w = (blockIdx.x * blockDim.x + threadIdx.x) >> 5;
    int lane = threadIdx.x & 31;
    if (w >= NN) return;
    int beg = rp[w], end = rp[w + 1];
    float4 a0 = {0.f, 0.f, 0.f, 0.f}, a1 = a0, a2 = a0, a3 = a0;
    int e = beg;
    for (; e + 4 <= end; e += 4) {
        int s0 = ss[e], s1 = ss[e + 1], s2 = ss[e + 2], s3 = ss[e + 3];
        uint2 v0 = ((const uint2*)(xsrc + (size_t)s0 * C))[lane];
        uint2 v1 = ((const uint2*)(xsrc + (size_t)s1 * C))[lane];
        uint2 v2 = ((const uint2*)(xsrc + (size_t)s2 * C))[lane];
        uint2 v3 = ((const uint2*)(xsrc + (size_t)s3 * C))[lane];
        f4add(a0, h2f4(v0)); f4add(a1, h2f4(v1)); f4add(a2, h2f4(v2)); f4add(a3, h2f4(v3));
    }
    for (; e < end; ++e) {
        int s = ss[e];
        f4add(a0, h2f4(((const uint2*)(xsrc + (size_t)s * C))[lane]));
    }
    f4add(a0, a1); f4add(a2, a3); f4add(a0, a2);
    int d = end - beg;
    float inv = 1.0f / (float)(d > 1 ? d : 1);
    uint2 h, l;
    split2(a0.x * inv, a0.y * inv, h.x, l.x);
    split2(a0.z * inv, a0.w * inv, h.y, l.y);
    *(uint2*)(oh + (size_t)w * C + lane * 4) = h;
    *(uint2*)(ol + (size_t)w * C + lane * 4) = l;
}

// ---------------- weight prep: concat + bf16 hi/lo split ----------------
__global__ void prep_user(const float* __restrict__ Wl_iu, const float* __restrict__ b_iu, const float* __restrict__ Wr_iu,
                          const float* __restrict__ Wl_uu, const float* __restrict__ b_uu, const float* __restrict__ Wr_uu,
                          bf16* __restrict__ Wh, bf16* __restrict__ Wl, float* __restrict__ bv) {
    int i = blockIdx.x * blockDim.x + threadIdx.x;
    if (i < C * 384) {
        int c = i / 384, k = i - c * 384;
        float v;
        if (k < 128)      v = Wl_iu[c * 128 + k];
        else if (k < 256) v = Wl_uu[c * 128 + k - 128];
        else              v = Wr_iu[c * 128 + k - 256] + Wr_uu[c * 128 + k - 256];
        bf16 h = __float2bfloat16(v);
        Wh[i] = h;
        Wl[i] = __float2bfloat16(v - __bfloat162float(h));
        if (i < C) bv[i] = b_iu[i] + b_uu[i];
    }
}

__global__ void prep_item(const float* __restrict__ Wl_ui, const float* __restrict__ b_ui, const float* __restrict__ Wr_ui,
                          bf16* __restrict__ Wh, bf16* __restrict__ Wl, float* __restrict__ bv) {
    int i = blockIdx.x * blockDim.x + threadIdx.x;
    if (i < C * 256) {
        int c = i / 256, k = i - c * 256;
        float v = (k < 128) ? Wl_ui[c * 128 + k] : Wr_ui[c * 128 + k - 128];
        bf16 h = __float2bfloat16(v);
        Wh[i] = h;
        Wl[i] = __float2bfloat16(v - __bfloat162float(h));
        if (i < C) bv[i] = b_ui[i];
    }
}

// ---------------- mma.sync helpers ----------------
__device__ __forceinline__ uint32_t smem_u32(const void* p) {
    uint32_t a;
    asm("{ .reg .u64 t; cvta.to.shared.u64 t, %1; cvt.u32.u64 %0, t; }" : "=r"(a) : "l"(p));
    return a;
}

#define LDM4(r, addr) \
    asm volatile("ldmatrix.sync.aligned.m8n8.x4.shared.b16 {%0,%1,%2,%3}, [%4];" \
        : "=r"((r)[0]), "=r"((r)[1]), "=r"((r)[2]), "=r"((r)[3]) : "r"(addr))

#define MMA16816(d, a, b0, b1) \
    asm volatile("mma.sync.aligned.m16n8k16.row.col.f32.bf16.bf16.f32 " \
        "{%0,%1,%2,%3},{%4,%5,%6,%7},{%8,%9},{%0,%1,%2,%3};" \
        : "+f"((d)[0]), "+f"((d)[1]), "+f"((d)[2]), "+f"((d)[3]) \
        : "r"((a)[0]), "r"((a)[1]), "r"((a)[2]), "r"((a)[3]), "r"(b0), "r"(b1))

__device__ __forceinline__ void cp16(uint32_t dst, const void* src, bool pred) {
    int sz = pred ? 16 : 0;
    asm volatile("cp.async.cg.shared.global [%0], [%1], 16, %2;" :: "r"(dst), "l"(src), "r"(sz));
}
__device__ __forceinline__ void cp_commit() { asm volatile("cp.async.commit_group;"); }
__device__ __forceinline__ void cp_wait1() { asm volatile("cp.async.wait_group 1;"); }

// ---------------- cp.async double-buffered HMMA GEMM + bias + LN + ReLU ----------------
#define BUF_STRIDE 73728
#define SA_HI 0
#define SA_LO 18432
#define SB_HI 36864
#define SB_LO 55296
#define CTRL_OFF 147456
#define YS_PITCH 136
#define SMEM_BYTES (147456 + 1536)

template <int NCH>
__global__ void __launch_bounds__(256, 1)
gemm_mma(const bf16* __restrict__ Ah0, const bf16* __restrict__ Al0,
         const bf16* __restrict__ Ah1, const bf16* __restrict__ Al1,
         const bf16* __restrict__ Ah2, const bf16* __restrict__ Al2,
         const bf16* __restrict__ Whi, const bf16* __restrict__ Wlo,
         const float* __restrict__ bias, const float* __restrict__ lnw, const float* __restrict__ lnb,
         float* __restrict__ out, bf16* __restrict__ outh, bf16* __restrict__ outl,
         __half* __restrict__ outf, int n) {
    extern __shared__ __align__(16) char smp[];
    const int KTOT = NCH * 128;
    const int NC2 = NCH * 2;
    uint32_t sbase = smem_u32(smp);

    int tid = threadIdx.x, lane = tid & 31, wid = tid >> 5;
    int wr = wid >> 1, wc = wid & 1;
    int nodeBase = blockIdx.x * 128;

    float* sBias = (float*)(smp + CTRL_OFF);
    float* sLnw  = (float*)(smp + CTRL_OFF + 512);
    float* sLnb  = (float*)(smp + CTRL_OFF + 1024);
    if (tid < 128) { sBias[tid] = bias[tid]; sLnw[tid] = lnw[tid]; sLnb[tid] = lnb[tid]; }

    const bf16* AH[3] = {Ah0, Ah1, Ah2};
    const bf16* AL[3] = {Al0, Al1, Al2};

    float D[2][8][4];
#pragma unroll
    for (int a = 0; a < 2; a++)
#pragma unroll
        for (int b = 0; b < 8; b++)
#pragma unroll
            for (int c = 0; c < 4; c++) D[a][b][c] = 0.f;

    auto load_chunk = [&](int c2, int buf) {
        int srcIdx = c2 >> 1;
        int koff = (c2 & 1) * 64;
        const bf16* Ah = AH[srcIdx];
        const bf16* Al = AL[srcIdx];
        uint32_t bb = sbase + buf * BUF_STRIDE;
#pragma unroll
        for (int i = 0; i < 4; i++) {
            int j = i * 256 + tid;
            int row = j >> 3, q = j & 7;
            int node = nodeBase + row;
            bool ok = node < n;
            size_t ga = (size_t)(ok ? node : 0) * C + koff + q * 8;
            uint32_t off = row * 144 + q * 16;
            cp16(bb + SA_HI + off, Ah + ga, ok);
            cp16(bb + SA_LO + off, Al + ga, ok);
        }
#pragma unroll
        for (int i = 0; i < 4; i++) {
            int j = i * 256 + tid;
            int row = j >> 3, q = j & 7;
            size_t ga = (size_t)row * KTOT + c2 * 64 + q * 8;
            uint32_t off = row * 144 + q * 16;
            cp16(bb + SB_HI + off, Whi + ga, true);
            cp16(bb + SB_LO + off, Wlo + ga, true);
        }
    };

    load_chunk(0, 0);
    cp_commit();

#pragma unroll
    for (int c2 = 0; c2 < NC2; c2++) {
        if (c2 + 1 < NC2) load_chunk(c2 + 1, (c2 + 1) & 1);
        cp_commit();
        cp_wait1();
        __syncthreads();
        uint32_t bb = sbase + (c2 & 1) * BUF_STRIDE;
#pragma unroll
        for (int s = 0; s < 4; s++) {
            uint32_t ah[2][4], al[2][4], bh[4][4], bl[4][4];
#pragma unroll
            for (int mt = 0; mt < 2; mt++) {
                int row = wr * 32 + mt * 16 + (lane & 15);
                int kb = s * 32 + (lane >> 4) * 16;
                uint32_t ad = bb + SA_HI + row * 144 + kb;
                LDM4(ah[mt], ad);
                LDM4(al[mt], ad + (SA_LO - SA_HI));
            }
#pragma unroll
            for (int bt = 0; bt < 4; bt++) {
                int rown = wc * 64 + bt * 16 + ((lane >> 4) * 8 + (lane & 7));
                int kb = s * 32 + ((lane >> 3) & 1) * 16;
                uint32_t ad = bb + SB_HI + rown * 144 + kb;
                LDM4(bh[bt], ad);
                LDM4(bl[bt], ad + (SB_LO - SB_HI));
            }
#pragma unroll
            for (int mt = 0; mt < 2; mt++)
#pragma unroll
                for (int bt = 0; bt < 4; bt++) {
                    MMA16816(D[mt][bt * 2],     ah[mt], bh[bt][0], bh[bt][1]);
                    MMA16816(D[mt][bt * 2 + 1], ah[mt], bh[bt][2], bh[bt][3]);
                    MMA16816(D[mt][bt * 2],     ah[mt], bl[bt][0], bl[bt][1]);
                    MMA16816(D[mt][bt * 2 + 1], ah[mt], bl[bt][2], bl[bt][3]);
                    MMA16816(D[mt][bt * 2],     al[mt], bh[bt][0], bh[bt][1]);
                    MMA16816(D[mt][bt * 2 + 1], al[mt], bh[bt][2], bh[bt][3]);
                }
        }
        __syncthreads();
    }

    // ---- epilogue: accum + bias -> smem, LN + ReLU, optional fp32/bf16-split/fp16 stores ----
    float* ys = (float*)smp;
#pragma unroll
    for (int mt = 0; mt < 2; mt++) {
        int r0 = wr * 32 + mt * 16 + (lane >> 2);
#pragma unroll
        for (int bt = 0; bt < 8; bt++) {
            int nn = wc * 64 + bt * 8 + (lane & 3) * 2;
            float b0 = sBias[nn], b1 = sBias[nn + 1];
            float2 v0 = {D[mt][bt][0] + b0, D[mt][bt][1] + b1};
            float2 v1 = {D[mt][bt][2] + b0, D[mt][bt][3] + b1};
            *(float2*)&ys[r0 * YS_PITCH + nn] = v0;
            *(float2*)&ys[(r0 + 8) * YS_PITCH + nn] = v1;
        }
    }
    __syncthreads();
    if (tid < 128) {
        int row = tid;
        float s = 0.f, s2 = 0.f;
#pragma unroll
        for (int c = 0; c < 128; c++) {
            float v = ys[row * YS_PITCH + c];
            s += v; s2 += v * v;
        }
        float mu = s * (1.f / 128.f);
        float rs = rsqrtf(s2 * (1.f / 128.f) - mu * mu + 1e-5f);
#pragma unroll
        for (int c = 0; c < 128; c++) {
            float y = (ys[row * YS_PITCH + c] - mu) * rs * sLnw[c] + sLnb[c];
            ys[row * YS_PITCH + c] = fmaxf(y, 0.f);
        }
    }
    __syncthreads();
#pragma unroll 4
    for (int i = 0; i < 32; i++) {
        int j = i * 256 + tid;
        int row = j >> 6, cp = (j & 63) * 2;
        int node = nodeBase + row;
        if (node < n) {
            float v0 = ys[row * YS_PITCH + cp];
            float v1 = ys[row * YS_PITCH + cp + 1];
            if (out) *(float2*)(out + (size_t)node * C + cp) = make_float2(v0, v1);
            if (outh) {
                uint32_t h, l;
                split2(v0, v1, h, l);
                *(uint32_t*)(outh + (size_t)node * C + cp) = h;
                *(uint32_t*)(outl + (size_t)node * C + cp) = l;
            }
            if (outf) {
                __half2 hv = __floats2half2_rn(v0, v1);
                *(__half2*)(outf + (size_t)node * C + cp) = hv;
            }
        }
    }
}

// ---------------- host launch ----------------
extern "C" void kernel_launch(void* const* d_in, const int* in_sizes, int n_in,
                              void* d_out, int out_size) {
    const float* x_user = (const float*)d_in[0];
    const float* x_item = (const float*)d_in[1];
    const int* E0 = (const int*)d_in[2];
    const int* E1 = (const int*)d_in[3];
    const int* E2 = (const int*)d_in[4];

    int *deg, *rowptr, *cursor, *srcs, *bsum, *bofs;
    float *bv;
    bf16 *x0h, *x0l, *x1h, *x1l, *aggh, *aggl, *wuh, *wul, *wih, *wil;
    __half *x0f, *x1f;
    cudaGetSymbolAddress((void**)&deg, g_deg);
    cudaGetSymbolAddress((void**)&rowptr, g_rowptr);
    cudaGetSymbolAddress((void**)&cursor, g_cursor);
    cudaGetSymbolAddress((void**)&srcs, g_srcs);
    cudaGetSymbolAddress((void**)&bsum, g_bsum);
    cudaGetSymbolAddress((void**)&bofs, g_bofs);
    cudaGetSymbolAddress((void**)&x0h, g_x0h);
    cudaGetSymbolAddress((void**)&x0l, g_x0l);
    cudaGetSymbolAddress((void**)&x1h, g_x1h);
    cudaGetSymbolAddress((void**)&x1l, g_x1l);
    cudaGetSymbolAddress((void**)&x0f, g_x0f);
    cudaGetSymbolAddress((void**)&x1f, g_x1f);
    cudaGetSymbolAddress((void**)&aggh, g_aggh);
    cudaGetSymbolAddress((void**)&aggl, g_aggl);
    cudaGetSymbolAddress((void**)&bv, g_b);
    cudaGetSymbolAddress((void**)&wuh, g_Wuh);
    cudaGetSymbolAddress((void**)&wul, g_Wul);
    cudaGetSymbolAddress((void**)&wih, g_Wih);
    cudaGetSymbolAddress((void**)&wil, g_Wil);

    cudaFuncSetAttribute(gemm_mma<3>, cudaFuncAttributeMaxDynamicSharedMemorySize, SMEM_BYTES);
    cudaFuncSetAttribute(gemm_mma<2>, cudaFuncAttributeMaxDynamicSharedMemorySize, SMEM_BYTES);

    const size_t NC = (size_t)NN * C;
    bf16* Ah[2][3]; bf16* Al[2][3];
    for (int L = 0; L < 2; L++)
        for (int t = 0; t < 3; t++) {
            Ah[L][t] = aggh + (size_t)L * 3 * NC + (size_t)t * NC;
            Al[L][t] = aggl + (size_t)L * 3 * NC + (size_t)t * NC;
        }

    cudaStream_t s2;
    cudaStreamCreateWithFlags(&s2, cudaStreamNonBlocking);
    cudaEvent_t ev0, evPrep, evAgg0, evItem0, evAgg1, evItem1;
    cudaEventCreateWithFlags(&ev0, cudaEventDisableTiming);
    cudaEventCreateWithFlags(&evPrep, cudaEventDisableTiming);
    cudaEventCreateWithFlags(&evAgg0, cudaEventDisableTiming);
    cudaEventCreateWithFlags(&evItem0, cudaEventDisableTiming);
    cudaEventCreateWithFlags(&evAgg1, cudaEventDisableTiming);
    cudaEventCreateWithFlags(&evItem1, cudaEventDisableTiming);

    const float* lnw[2][2]; const float* lnb[2][2];
    for (int L = 0; L < 2; L++) {
        int pb = 5 + L * 13;
        lnw[L][0] = (const float*)d_in[pb + 9];  lnb[L][0] = (const float*)d_in[pb + 10];
        lnw[L][1] = (const float*)d_in[pb + 11]; lnb[L][1] = (const float*)d_in[pb + 12];
    }

    // fork s2 from main at start
    cudaEventRecord(ev0, 0);
    cudaStreamWaitEvent(s2, ev0, 0);

    // ---- s2: splits + weight prep ----
    split_x<<<dim3(1024, 2), 256, 0, s2>>>(x_user, x_item, x0h, x0l, x0f);
    for (int L = 0; L < 2; L++) {
        int pb = 5 + L * 13;
        prep_user<<<(C * 384 + 255) / 256, 256, 0, s2>>>(
            (const float*)d_in[pb + 3], (const float*)d_in[pb + 4], (const float*)d_in[pb + 5],
            (const float*)d_in[pb + 6], (const float*)d_in[pb + 7], (const float*)d_in[pb + 8],
            wuh + (size_t)L * C * 384, wul + (size_t)L * C * 384, bv + L * 2 * C);
        prep_item<<<(C * 256 + 255) / 256, 256, 0, s2>>>(
            (const float*)d_in[pb + 0], (const float*)d_in[pb + 1], (const float*)d_in[pb + 2],
            wih + (size_t)L * C * 256, wil + (size_t)L * C * 256, bv + L * 2 * C + C);
    }
    cudaEventRecord(evPrep, s2);

    // ---- main: CSR build ----
    zero_int<<<256, 256>>>(deg, 3 * NN);
    histo3<<<dim3(512, 3), 256>>>(E0, E1, E2, deg);
    scan_partial<<<dim3(NB, 3), 256>>>(deg, bsum);
    scan_bsum<<<1, 96>>>(bsum, bofs);
    scan_final<<<dim3(NB, 3), 256>>>(deg, bofs, rowptr, cursor);
    fillcsr3<<<dim3(512, 3), 256>>>(E0, E1, E2, cursor, srcs);

    const int AGG_BLK = (NN + 7) / 8;
    const int GG = (NN + 127) / 128;

    // ---- layer 0 ----
    cudaStreamWaitEvent(0, evPrep, 0);
    agg3<<<dim3(AGG_BLK, 3), 256>>>(x0f, x0f + NC, rowptr, srcs, aggh, aggl);
    cudaEventRecord(evAgg0, 0);

    cudaStreamWaitEvent(s2, evAgg0, 0);
    gemm_mma<2><<<GG, 256, SMEM_BYTES, s2>>>(Ah[0][0], Al[0][0], x0h + NC, x0l + NC, nullptr, nullptr,
                                             wih, wil, bv + C, lnw[0][1], lnb[0][1],
                                             nullptr, x1h + NC, x1l + NC, x1f + NC, NN);
    cudaEventRecord(evItem0, s2);

    gemm_mma<3><<<GG, 256, SMEM_BYTES>>>(Ah[0][1], Al[0][1], Ah[0][2], Al[0][2], x0h, x0l,
                                         wuh, wul, bv, lnw[0][0], lnb[0][0],
                                         nullptr, x1h, x1l, x1f, NN);

    // ---- layer 1 ----
    cudaStreamWaitEvent(0, evItem0, 0);
    agg3<<<dim3(AGG_BLK, 3), 256>>>(x1f, x1f + NC, rowptr, srcs, aggh + 3 * NC, aggl + 3 * NC);
    cudaEventRecord(evAgg1, 0);

    cudaStreamWaitEvent(s2, evAgg1, 0);
    gemm_mma<2><<<GG, 256, SMEM_BYTES, s2>>>(Ah[1][0], Al[1][0], x1h + NC, x1l + NC, nullptr, nullptr,
                                             wih + (size_t)C * 256, wil + (size_t)C * 256, bv + 2 * C + C,
                                             lnw[1][1], lnb[1][1],
                                             (float*)d_out + NC, nullptr, nullptr, nullptr, NN);
    cudaEventRecord(evItem1, s2);

    gemm_mma<3><<<GG, 256, SMEM_BYTES>>>(Ah[1][1], Al[1][1], Ah[1][2], Al[1][2], x1h, x1l,
                                         wuh + (size_t)C * 384, wul + (size_t)C * 384, bv + 2 * C,
                                         lnw[1][0], lnb[1][0],
                                         (float*)d_out, nullptr, nullptr, nullptr, NN);
    cudaStreamWaitEvent(0, evItem1, 0);
}